// round 15
// baseline (speedup 1.0000x reference)
#include <cuda_runtime.h>
#include <cstdint>

// ---------------------------------------------------------------------------
// y = W8(...(W0 x + b0)...) + b8  ->  y = W_eff x + b_eff,  W_eff [10,784].
// R14: gemv with BLOCK-LEVEL 2-stage cp.async pipeline:
//   320 threads stage 160x32 tiles cooperatively; compute in (rg,kg) layout.
//   71KB smem -> 3 CTAs/SM; grid 410 <= 444 -> single wave.
// ---------------------------------------------------------------------------

#define K_IN   784
#define N_OUT  10
#define RPB    160        // rows per CTA (10 warps x 16)
#define TILEC  32         // cols per tile
#define TILEF  (RPB * TILEC)   // floats per stage (5120 = 20KB)
#define NTILE  25         // 24 full + 1 half (16-col) tile

__device__ float g_Weff[N_OUT * K_IN];
__device__ float g_beff[N_OUT];

// ---------------------------------------------------------------------------
// fold_fused: 7 CTAs x 768 threads (unchanged, known-correct).
// ---------------------------------------------------------------------------
template<int N, int M>
__device__ __forceinline__ void fold_step(float* A, float* T, float* beff,
    const float* W, const float* b, int t)
{
    if (t < N_OUT) {
        float s = 0.f;
#pragma unroll
        for (int k = 0; k < N; ++k) s += A[t * N + k] * b[k];
        beff[t] += s;
    }
    if (t < N_OUT * M) {
        int r = t / M, c = t - r * M;
        float s = 0.f;
#pragma unroll
        for (int k = 0; k < N; ++k) s += A[r * N + k] * W[k * M + c];
        T[t] = s;
    }
    __syncthreads();
    if (t < N_OUT * M) A[t] = T[t];
    __syncthreads();
}

__global__ __launch_bounds__(768) void fold_fused(
    const float* __restrict__ W0, const float* __restrict__ b0,
    const float* __restrict__ W1, const float* __restrict__ b1,
    const float* __restrict__ W2, const float* __restrict__ b2,
    const float* __restrict__ W3, const float* __restrict__ b3,
    const float* __restrict__ W4, const float* __restrict__ b4,
    const float* __restrict__ W5, const float* __restrict__ b5,
    const float* __restrict__ W6, const float* __restrict__ b6,
    const float* __restrict__ W7, const float* __restrict__ b7,
    const float* __restrict__ W8, const float* __restrict__ b8)
{
    __shared__ float A[10 * 69], T[10 * 69], beff[N_OUT];
    __shared__ float sw[3049];
    __shared__ float sbv[170];

    const int t = threadIdx.x;

    float* sW1 = sw;          float* sW2 = sw + 2139;
    float* sW3 = sw + 2449;   float* sW4 = sw + 2549;
    float* sW5 = sw + 2649;   float* sW6 = sw + 2749;
    float* sW7 = sw + 2849;   float* sW8 = sw + 2949;
    float* sb0 = sbv;         float* sb1 = sbv + 69;
    float* sb2 = sbv + 100;   float* sb3 = sbv + 110;
    float* sb4 = sbv + 120;   float* sb5 = sbv + 130;
    float* sb6 = sbv + 140;   float* sb7 = sbv + 150;
    float* sb8 = sbv + 160;

    for (int i = t; i < 2139; i += 768) sW1[i] = W1[i];
    if (t < 310) sW2[t] = W2[t];
    if (t < 100) { sW3[t] = W3[t]; sW4[t] = W4[t]; sW5[t] = W5[t];
                   sW6[t] = W6[t]; sW7[t] = W7[t]; sW8[t] = W8[t]; }
    if (t < 69) sb0[t] = b0[t];
    if (t < 31) sb1[t] = b1[t];
    if (t < 10) { sb2[t] = b2[t]; sb3[t] = b3[t]; sb4[t] = b4[t];
                  sb5[t] = b5[t]; sb6[t] = b6[t]; sb7[t] = b7[t];
                  sb8[t] = b8[t]; }
    __syncthreads();

    if (t < 100) A[t] = sW8[t];
    if (t < N_OUT) beff[t] = sb8[t];
    __syncthreads();

    fold_step<10, 10>(A, T, beff, sW7, sb7, t);
    fold_step<10, 10>(A, T, beff, sW6, sb6, t);
    fold_step<10, 10>(A, T, beff, sW5, sb5, t);
    fold_step<10, 10>(A, T, beff, sW4, sb4, t);
    fold_step<10, 10>(A, T, beff, sW3, sb3, t);
    fold_step<10, 31>(A, T, beff, sW2, sb2, t);
    fold_step<31, 69>(A, T, beff, sW1, sb1, t);   // A now [10,69]

    if (blockIdx.x == 0 && t < N_OUT) {
        float s = 0.f;
#pragma unroll
        for (int k = 0; k < 69; ++k) s += A[t * 69 + k] * sb0[k];
        g_beff[t] = beff[t] + s;
    }

    if (t < 112) {
        const int col = blockIdx.x * 112 + t;
        float acc[N_OUT];
#pragma unroll
        for (int r = 0; r < N_OUT; ++r) acc[r] = 0.f;
#pragma unroll
        for (int k = 0; k < 69; ++k) {
            float w0 = W0[k * K_IN + col];
#pragma unroll
            for (int r = 0; r < N_OUT; ++r) acc[r] += A[r * 69 + k] * w0;
        }
#pragma unroll
        for (int r = 0; r < N_OUT; ++r) g_Weff[r * K_IN + col] = acc[r];
    }
}

// ---------------------------------------------------------------------------
// gemv_pipe2
// ---------------------------------------------------------------------------
__device__ __forceinline__ void cp16(float* s, const float* g)
{
    unsigned saddr = (unsigned)__cvta_generic_to_shared(s);
    asm volatile("cp.async.cg.shared.global [%0], [%1], 16;\n"
                 :: "r"(saddr), "l"(g));
}

__global__ __launch_bounds__(320, 3) void gemv_pipe2(
    const float* __restrict__ x, float* __restrict__ y, int B)
{
    extern __shared__ float smem[];
    float* sW   = smem;               // 7840 + 16 pad
    float* sb   = smem + 7856;        // bias (region padded to 7872)
    float* xb0  = smem + 7872;        // stage 0
    float* xb1  = xb0 + TILEF;        // stage 1

    const int tid = threadIdx.x;
    const int rowbase = blockIdx.x * RPB;
    const float* xg = x + (size_t)rowbase * K_IN;

    // stage helper (lambda-free, inlined below via macro-ish function)
    // thread t stages 16 cp16: idx = i*320 + t -> row = idx/8, c16 = idx%8
    // src col = tile*32 + c16*4 ; guard row/col.
    // ---- issue tile 0 ----
    {
        float* dst = xb0;
#pragma unroll
        for (int i = 0; i < TILEF / (320 * 4); ++i) {     // 4 transfers
            int idx = i * 320 + tid;
            int row = idx >> 3, c16 = idx & 7;
            int grow = rowbase + row;
            const float* src = xg + (size_t)row * K_IN + 4 * c16;
            if (grow >= B) src = x + 4 * c16;              // clamp (benign)
            cp16(dst + row * TILEC + 4 * c16, src);
        }
        asm volatile("cp.async.commit_group;\n");
    }

    // stage sW AFTER issuing tile 0 (overlap DRAM latency)
    for (int i = tid; i < N_OUT * K_IN; i += 320) sW[i] = g_Weff[i];
    if (tid < 16) sW[N_OUT * K_IN + tid] = 0.f;
    if (tid < N_OUT) sb[tid] = g_beff[tid];

    const int lane = tid & 31;
    const int warp = tid >> 5;
    const int kg = lane & 7;            // 16B-column lane
    const int rg = lane >> 3;           // quarter-warp row group
    const int wrow = warp * 16 + rg * 4;     // warp-local first row

    float acc[N_OUT][4];
#pragma unroll
    for (int j = 0; j < N_OUT; ++j)
#pragma unroll
        for (int r = 0; r < 4; ++r) acc[j][r] = 0.f;

#pragma unroll 1
    for (int t = 0; t < NTILE; ++t) {
        // ---- issue tile t+1 into the other buffer ----
        if (t + 1 < NTILE) {
            float* dst = (t & 1) ? xb0 : xb1;    // tile t+1 buffer
            const int c0 = (t + 1) * TILEC;
#pragma unroll
            for (int i = 0; i < TILEF / (320 * 4); ++i) {
                int idx = i * 320 + tid;
                int row = idx >> 3, c16 = idx & 7;
                int gcol = c0 + 4 * c16;
                int grow = rowbase + row;
                const float* src = xg + (size_t)row * K_IN + gcol;
                if (grow >= B || gcol >= K_IN) src = x;    // clamp (benign)
                cp16(dst + row * TILEC + 4 * c16, src);
            }
            asm volatile("cp.async.commit_group;\n");
            asm volatile("cp.async.wait_group 1;\n");      // tile t done
        } else {
            asm volatile("cp.async.wait_group 0;\n");
        }
        __syncthreads();

        // ---- compute tile t ----
        const float* buf = (t & 1) ? xb1 : xb0;
        const int c = t * TILEC + 4 * kg;
        const bool cok = (c < K_IN);     // tail tile: kg>=4 has no data

        float4 xv[4];
#pragma unroll
        for (int r = 0; r < 4; ++r) {
            if (cok) {
                xv[r] = *reinterpret_cast<const float4*>(
                    buf + (wrow + r) * TILEC + 4 * kg);
            } else {
                xv[r].x = xv[r].y = xv[r].z = xv[r].w = 0.f;
            }
        }

#pragma unroll
        for (int j = 0; j < N_OUT; ++j) {
            // c <= 796 worst-case; sW pad covers overrun; x zeros -> harmless
            float4 w = *reinterpret_cast<const float4*>(&sW[j * K_IN + c]);
#pragma unroll
            for (int r = 0; r < 4; ++r) {
                acc[j][r] += xv[r].x * w.x;
                acc[j][r] += xv[r].y * w.y;
                acc[j][r] += xv[r].z * w.z;
                acc[j][r] += xv[r].w * w.w;
            }
        }
        __syncthreads();    // everyone done with buf before it's restaged
    }

    // ---- butterfly reduce over the 8 kg lanes ----
#pragma unroll
    for (int m = 1; m <= 4; m <<= 1)
#pragma unroll
        for (int j = 0; j < N_OUT; ++j)
#pragma unroll
            for (int r = 0; r < 4; ++r)
                acc[j][r] += __shfl_xor_sync(0xFFFFFFFFu, acc[j][r], m);

    // ---- stores: lanes kg=0..4 write float2 pair #kg for their 4 rows ----
    if (kg < 5) {
#pragma unroll
        for (int r = 0; r < 4; ++r) {
            const int row = rowbase + wrow + r;
            if (row < B) {
                float2 v;
                v.x = acc[2 * kg][r]     + sb[2 * kg];
                v.y = acc[2 * kg + 1][r] + sb[2 * kg + 1];
                *reinterpret_cast<float2*>(y + (size_t)row * N_OUT + 2 * kg) = v;
            }
        }
    }
}

// ---------------------------------------------------------------------------
extern "C" void kernel_launch(void* const* d_in, const int* in_sizes, int n_in,
                              void* d_out, int out_size)
{
    const float* x = (const float*)d_in[0];
    const float* W[9];
    const float* b[9];
    for (int i = 0; i < 9; ++i) {
        W[i] = (const float*)d_in[1 + 2 * i];
        b[i] = (const float*)d_in[2 + 2 * i];
    }
    const int B = in_sizes[0] / K_IN;

    fold_fused<<<7, 768>>>(W[0], b[0], W[1], b[1], W[2], b[2], W[3], b[3],
                           W[4], b[4], W[5], b[5], W[6], b[6], W[7], b[7],
                           W[8], b[8]);

    const int smem_bytes = (7872 + 2 * TILEF) * sizeof(float);   // ~71.6KB
    static bool attr_set = false;
    if (!attr_set) {
        cudaFuncSetAttribute(gemv_pipe2,
                             cudaFuncAttributeMaxDynamicSharedMemorySize,
                             smem_bytes);
        attr_set = true;
    }

    float* y = (float*)d_out;
    gemv_pipe2<<<(B + RPB - 1) / RPB, 320, smem_bytes>>>(x, y, B);
}

// round 16
// speedup vs baseline: 1.2536x; 1.2536x over previous
#include <cuda_runtime.h>
#include <cstdint>

// ---------------------------------------------------------------------------
// y = W8(...(W0 x + b0)...) + b8  ->  y = W_eff x + b_eff,  W_eff [10,784].
// R16: persistent gemv, warp-private cp.async DEPTH-4 ring, f32x2 accums,
//      8-row units stolen via global counter (seeded by fold -> replay-safe).
//      784 = 49 x 16-col chunks: no tail code. Lane stages & consumes its
//      own 16B -> wait_group is the only synchronization in the mainloop.
// ---------------------------------------------------------------------------

#define K_IN    784
#define N_OUT   10
#define GRID_G  444                  // 3 CTAs/SM x 148 SMs, single wave
#define NWARPS  (GRID_G * 8)         // 3552

__device__ float g_Weff[N_OUT * K_IN];
__device__ float g_beff[N_OUT];
__device__ int   g_ctr;

// ---------------------------------------------------------------------------
// fold_fused: 7 CTAs x 768 threads (known-correct). Also seeds g_ctr.
// ---------------------------------------------------------------------------
template<int N, int M>
__device__ __forceinline__ void fold_step(float* A, float* T, float* beff,
    const float* W, const float* b, int t)
{
    if (t < N_OUT) {
        float s = 0.f;
#pragma unroll
        for (int k = 0; k < N; ++k) s += A[t * N + k] * b[k];
        beff[t] += s;
    }
    if (t < N_OUT * M) {
        int r = t / M, c = t - r * M;
        float s = 0.f;
#pragma unroll
        for (int k = 0; k < N; ++k) s += A[r * N + k] * W[k * M + c];
        T[t] = s;
    }
    __syncthreads();
    if (t < N_OUT * M) A[t] = T[t];
    __syncthreads();
}

__global__ __launch_bounds__(768) void fold_fused(
    const float* __restrict__ W0, const float* __restrict__ b0,
    const float* __restrict__ W1, const float* __restrict__ b1,
    const float* __restrict__ W2, const float* __restrict__ b2,
    const float* __restrict__ W3, const float* __restrict__ b3,
    const float* __restrict__ W4, const float* __restrict__ b4,
    const float* __restrict__ W5, const float* __restrict__ b5,
    const float* __restrict__ W6, const float* __restrict__ b6,
    const float* __restrict__ W7, const float* __restrict__ b7,
    const float* __restrict__ W8, const float* __restrict__ b8)
{
    __shared__ float A[10 * 69], T[10 * 69], beff[N_OUT];
    __shared__ float sw[3049];
    __shared__ float sbv[170];

    const int t = threadIdx.x;

    if (blockIdx.x == 0 && t == 0) g_ctr = NWARPS;   // seed stealer

    float* sW1 = sw;          float* sW2 = sw + 2139;
    float* sW3 = sw + 2449;   float* sW4 = sw + 2549;
    float* sW5 = sw + 2649;   float* sW6 = sw + 2749;
    float* sW7 = sw + 2849;   float* sW8 = sw + 2949;
    float* sb0 = sbv;         float* sb1 = sbv + 69;
    float* sb2 = sbv + 100;   float* sb3 = sbv + 110;
    float* sb4 = sbv + 120;   float* sb5 = sbv + 130;
    float* sb6 = sbv + 140;   float* sb7 = sbv + 150;
    float* sb8 = sbv + 160;

    for (int i = t; i < 2139; i += 768) sW1[i] = W1[i];
    if (t < 310) sW2[t] = W2[t];
    if (t < 100) { sW3[t] = W3[t]; sW4[t] = W4[t]; sW5[t] = W5[t];
                   sW6[t] = W6[t]; sW7[t] = W7[t]; sW8[t] = W8[t]; }
    if (t < 69) sb0[t] = b0[t];
    if (t < 31) sb1[t] = b1[t];
    if (t < 10) { sb2[t] = b2[t]; sb3[t] = b3[t]; sb4[t] = b4[t];
                  sb5[t] = b5[t]; sb6[t] = b6[t]; sb7[t] = b7[t];
                  sb8[t] = b8[t]; }
    __syncthreads();

    if (t < 100) A[t] = sW8[t];
    if (t < N_OUT) beff[t] = sb8[t];
    __syncthreads();

    fold_step<10, 10>(A, T, beff, sW7, sb7, t);
    fold_step<10, 10>(A, T, beff, sW6, sb6, t);
    fold_step<10, 10>(A, T, beff, sW5, sb5, t);
    fold_step<10, 10>(A, T, beff, sW4, sb4, t);
    fold_step<10, 10>(A, T, beff, sW3, sb3, t);
    fold_step<10, 31>(A, T, beff, sW2, sb2, t);
    fold_step<31, 69>(A, T, beff, sW1, sb1, t);   // A now [10,69]

    if (blockIdx.x == 0 && t < N_OUT) {
        float s = 0.f;
#pragma unroll
        for (int k = 0; k < 69; ++k) s += A[t * 69 + k] * sb0[k];
        g_beff[t] = beff[t] + s;
    }

    if (t < 112) {
        const int col = blockIdx.x * 112 + t;
        float acc[N_OUT];
#pragma unroll
        for (int r = 0; r < N_OUT; ++r) acc[r] = 0.f;
#pragma unroll
        for (int k = 0; k < 69; ++k) {
            float w0 = W0[k * K_IN + col];
#pragma unroll
            for (int r = 0; r < N_OUT; ++r) acc[r] += A[r * 69 + k] * w0;
        }
#pragma unroll
        for (int r = 0; r < N_OUT; ++r) g_Weff[r * K_IN + col] = acc[r];
    }
}

// ---------------------------------------------------------------------------
// gemv_steal
// ---------------------------------------------------------------------------
__device__ __forceinline__ void cp16(float* s, const float* g)
{
    unsigned saddr = (unsigned)__cvta_generic_to_shared(s);
    asm volatile("cp.async.cg.shared.global [%0], [%1], 16;\n"
                 :: "r"(saddr), "l"(g));
}

__device__ __forceinline__ void ffma2(unsigned long long& acc,
                                      unsigned long long a,
                                      unsigned long long b)
{
    asm("fma.rn.f32x2 %0, %1, %2, %0;" : "+l"(acc) : "l"(a), "l"(b));
}

__global__ __launch_bounds__(256, 3) void gemv_steal(
    const float* __restrict__ x, float* __restrict__ y, int B)
{
    __shared__ float sW[N_OUT * K_IN];     // 31360 B (no pad needed: 49x16)
    __shared__ float sb[16];
    __shared__ float ring[8 * 4 * 128];    // warp x 4 slots x (8 rows x 16 c)

    const int tid = threadIdx.x;
    for (int i = tid; i < N_OUT * K_IN; i += 256) sW[i] = g_Weff[i];
    if (tid < N_OUT) sb[tid] = g_beff[tid];
    __syncthreads();

    const int lane = tid & 31;
    const int warp = tid >> 5;
    const int rg  = lane >> 2;          // row 0..7 within unit
    const int kg4 = lane & 3;           // 4-col slice within 16-col chunk
    const int co  = 4 * kg4;

    const long NU = (long)(B >> 3);     // 8-row units (B = 65536 -> 8192)
    // lane-invariant ring base for THIS lane's 16B in each slot
    float* myring = ring + warp * 512 + rg * 16 + co;

    long u_cur = (long)blockIdx.x * 8 + warp;
    if (u_cur >= NU) return;
    long base_cur = u_cur * 8;

    // grab next unit (counter pre-seeded to NWARPS by fold_fused)
    int un = 0;
    if (lane == 0) un = atomicAdd(&g_ctr, 1);
    un = __shfl_sync(0xFFFFFFFFu, un, 0);
    bool has_nxt = (un < NU);

    // per-unit lane source pointers: x + (base + rg)*784 + co
    const float* pc = x + (base_cur + rg) * K_IN + co;
    const float* pn = x + ((long)un * 8 + rg) * K_IN + co;

    // prologue: stage chunks 0..2 of current unit
#pragma unroll
    for (int s = 0; s < 3; ++s) {
        cp16(myring + s * 128, pc + s * 16);
        asm volatile("cp.async.commit_group;\n");
    }

    unsigned long long accA[N_OUT], accB[N_OUT];
#pragma unroll
    for (int j = 0; j < N_OUT; ++j) { accA[j] = 0ull; accB[j] = 0ull; }

    int k = 0;   // global chunk counter (ring phase)
    for (;;) {
#pragma unroll 1
        for (int i = 0; i < 49; ++i) {
            // stage chunk i+3 (crossing into next unit near the end)
            const int st = i + 3;
            float* slot3 = myring + ((k + 3) & 3) * 128;
            if (st < 49) {
                cp16(slot3, pc + st * 16);
            } else if (has_nxt) {
                cp16(slot3, pn + (st - 49) * 16);
            }
            asm volatile("cp.async.commit_group;\n");
            asm volatile("cp.async.wait_group 3;\n");   // chunk i ready

            // consume own 16B of chunk i
            ulonglong2 xv = *reinterpret_cast<const ulonglong2*>(
                myring + (k & 3) * 128);
            const float* wp = sW + i * 16 + co;
#pragma unroll
            for (int j = 0; j < N_OUT; ++j) {
                ulonglong2 w = *reinterpret_cast<const ulonglong2*>(
                    wp + j * K_IN);
                ffma2(accA[j], xv.x, w.x);
                ffma2(accB[j], xv.y, w.y);
            }
            ++k;
        }

        // ---- epilogue for this unit: unpack, kg-butterfly, store, reset ----
        float s[N_OUT];
#pragma unroll
        for (int j = 0; j < N_OUT; ++j) {
            float a0, a1, b0, b1;
            asm("mov.b64 {%0, %1}, %2;" : "=f"(a0), "=f"(a1) : "l"(accA[j]));
            asm("mov.b64 {%0, %1}, %2;" : "=f"(b0), "=f"(b1) : "l"(accB[j]));
            s[j] = (a0 + a1) + (b0 + b1);
            accA[j] = 0ull; accB[j] = 0ull;
        }
#pragma unroll
        for (int m = 1; m <= 2; m <<= 1)
#pragma unroll
            for (int j = 0; j < N_OUT; ++j)
                s[j] += __shfl_xor_sync(0xFFFFFFFFu, s[j], m);

        const long row = base_cur + rg;
        if (row < B) {
            float2 v;
            v.x = s[2 * kg4]     + sb[2 * kg4];
            v.y = s[2 * kg4 + 1] + sb[2 * kg4 + 1];
            *reinterpret_cast<float2*>(y + row * N_OUT + 2 * kg4) = v;
            if (kg4 == 0) {
                float2 w2;
                w2.x = s[8] + sb[8];
                w2.y = s[9] + sb[9];
                *reinterpret_cast<float2*>(y + row * N_OUT + 8) = w2;
            }
        }

        if (!has_nxt) break;
        base_cur = (long)un * 8;
        pc = pn;
        // steal the next unit (latency hidden behind 46 chunks)
        if (lane == 0) un = atomicAdd(&g_ctr, 1);
        un = __shfl_sync(0xFFFFFFFFu, un, 0);
        has_nxt = (un < NU);
        pn = x + ((long)un * 8 + rg) * K_IN + co;
    }
}

// ---------------------------------------------------------------------------
extern "C" void kernel_launch(void* const* d_in, const int* in_sizes, int n_in,
                              void* d_out, int out_size)
{
    const float* x = (const float*)d_in[0];
    const float* W[9];
    const float* b[9];
    for (int i = 0; i < 9; ++i) {
        W[i] = (const float*)d_in[1 + 2 * i];
        b[i] = (const float*)d_in[2 + 2 * i];
    }
    const int B = in_sizes[0] / K_IN;

    fold_fused<<<7, 768>>>(W[0], b[0], W[1], b[1], W[2], b[2], W[3], b[3],
                           W[4], b[4], W[5], b[5], W[6], b[6], W[7], b[7],
                           W[8], b[8]);

    float* y = (float*)d_out;
    gemv_steal<<<GRID_G, 256>>>(x, y, B);
}